// round 7
// baseline (speedup 1.0000x reference)
#include <cuda_runtime.h>
#include <cuda_bf16.h>
#include <math.h>

#define NB 4096
#define NL 8192
#define NT 256
#define NCH 4                       // chunks per row
#define CHUNK (NL / NCH)            // 2048 elements
#define GRID (NB * NCH)             // 16384 blocks
#define FXSCALE 16777216.0f         // 2^24 fixed-point scale for loss

// Packed counter fields: tp [0:10), tn [10:20), gp [20:32)
#define F_TP 1
#define F_TN (1 << 10)
#define F_GP (1 << 20)

// Global accumulators (integer -> order-independent -> deterministic).
__device__ unsigned long long g_loss_fx = 0;
__device__ int      g_tp_acc = 0;
__device__ int      g_tn_acc = 0;
__device__ int      g_gp_acc = 0;
__device__ int      g_valid  = 0;
__device__ unsigned g_done   = 0;

__device__ __forceinline__ void acc_elem(float p, float t, float& lg_sum, int& cnt) {
    p = (p - p == 0.0f) ? p : 0.0f;         // torch.where(isnan|isinf, 0, pred)
    bool tb = (t > 0.0f);                   // truth is exactly 0.0 or 1.0
    float x  = tb ? p : (1.0f - p);
    lg_sum += fmaxf(__logf(x), -100.0f);    // __logf(0) = -inf -> clamp
    bool pb = (p > 0.5f);
    // tb&&pb -> tp+gp ; tb&&!pb -> gp ; !tb&&!pb -> tn ; !tb&&pb -> 0
    cnt += tb ? (pb ? (F_TP + F_GP) : F_GP) : (pb ? 0 : F_TN);
}

__global__ void __launch_bounds__(NT) main_kernel(const float* __restrict__ pred,
                                                  const float* __restrict__ truth,
                                                  const int*   __restrict__ lengths,
                                                  float* __restrict__ out,
                                                  int out_size) {
    const int row   = blockIdx.x >> 2;       // NCH == 4
    const int chunk = blockIdx.x & (NCH - 1);
    const int len   = __ldg(lengths + row);
    const int start = chunk * CHUNK;
    const int v     = min(len - start, CHUNK);   // valid elems in this chunk

    if (v > 0) {
        const size_t off = (size_t)row * NL + start;
        const float4* __restrict__ p4 = reinterpret_cast<const float4*>(pred + off);
        const float4* __restrict__ t4 = reinterpret_cast<const float4*>(truth + off);

        float lg = 0.0f;
        int cnt = 0;

        const int n4 = v >> 2;
        #pragma unroll 2
        for (int i = threadIdx.x; i < n4; i += NT) {   // <= 2 iterations
            float4 p = __ldcs(&p4[i]);   // read-once stream: evict-first
            float4 t = __ldcs(&t4[i]);
            acc_elem(p.x, t.x, lg, cnt);
            acc_elem(p.y, t.y, lg, cnt);
            acc_elem(p.z, t.z, lg, cnt);
            acc_elem(p.w, t.w, lg, cnt);
        }
        const int base = n4 << 2;
        if ((int)threadIdx.x < v - base)
            acc_elem(pred[off + base + threadIdx.x],
                     truth[off + base + threadIdx.x], lg, cnt);

        // ---- block reduce (packed counters: warp-sum max 288/field, no overflow) ----
        #pragma unroll
        for (int s = 16; s > 0; s >>= 1) {
            lg  += __shfl_down_sync(0xffffffffu, lg,  s);
            cnt += __shfl_down_sync(0xffffffffu, cnt, s);
        }
        __shared__ float s_l[NT / 32];
        __shared__ int   s_tp[NT / 32], s_tn[NT / 32], s_gp[NT / 32];
        const int wid = threadIdx.x >> 5, lid = threadIdx.x & 31;
        if (lid == 0) {
            s_l[wid]  = lg;
            s_tp[wid] = cnt & 0x3ff;
            s_tn[wid] = (cnt >> 10) & 0x3ff;
            s_gp[wid] = (unsigned)cnt >> 20;
        }
        __syncthreads();
        if (threadIdx.x == 0) {
            float L = 0.0f; int a = 0, b = 0, c = 0;
            #pragma unroll
            for (int w = 0; w < NT / 32; w++) { L += s_l[w]; a += s_tp[w]; b += s_tn[w]; c += s_gp[w]; }
            float S = -L * __fdividef(1.0f, (float)len);   // chunk share of bce/len
            atomicAdd(&g_loss_fx, (unsigned long long)__float2ll_rn(S * FXSCALE));
            if (a) atomicAdd(&g_tp_acc, a);
            if (b) atomicAdd(&g_tn_acc, b);
            if (c) atomicAdd(&g_gp_acc, c);
        }
    }

    // ---- completion + O(1) finalize by last-done block's thread 0 ----
    if (threadIdx.x == 0) {
        if (chunk == 0 && len > 0) atomicAdd(&g_valid, len);
        __threadfence();
        unsigned t = atomicAdd(&g_done, 1u);
        if (t == (unsigned)(GRID - 1)) {
            unsigned long long fx = atomicAdd(&g_loss_fx, 0ULL);
            int TP = atomicAdd(&g_tp_acc, 0);
            int TN = atomicAdd(&g_tn_acc, 0);
            int GP = atomicAdd(&g_gp_acc, 0);
            int V  = atomicAdd(&g_valid, 0);
            int GN = V - GP;
            if (GP < 1) GP = 1;
            if (GN < 1) GN = 1;
            out[0] = (float)((double)fx / (double)FXSCALE / (double)NB);
            if (out_size > 1) out[1] = ((float)TP / (float)GP) * ((float)TN / (float)GN);
            g_loss_fx = 0ULL;
            g_tp_acc = 0; g_tn_acc = 0; g_gp_acc = 0; g_valid = 0;
            g_done = 0;
        }
    }
}

extern "C" void kernel_launch(void* const* d_in, const int* in_sizes, int n_in,
                              void* d_out, int out_size) {
    const float* pred    = (const float*)d_in[0];
    const float* truth   = (const float*)d_in[1];
    const int*   lengths = (const int*)d_in[2];
    float* out = (float*)d_out;

    main_kernel<<<GRID, NT>>>(pred, truth, lengths, out, out_size);
}